// round 1
// baseline (speedup 1.0000x reference)
#include <cuda_runtime.h>
#include <cuda_bf16.h>

#define B 32
#define N 100000
#define DEG 16
#define SEGS_PER_BLOCK 8   // 8 warps per block, one warp per segment

// Scratch: transposed x, shape (N, 32). 12.8 MB static device array (allowed).
__device__ float g_xT[(size_t)N * B];

// ---------------------------------------------------------------------------
// Kernel 1: transpose x (B=32, N) -> x_T (N, 32)
// Block (32, 8), tile 32x32 with padded smem to avoid bank conflicts.
// N = 100000 is divisible by 32, so no bounds checks needed.
// ---------------------------------------------------------------------------
__global__ __launch_bounds__(256) void transpose_kernel(const float* __restrict__ x,
                                                        float* __restrict__ xT) {
    __shared__ float tile[32][33];
    const int tx = threadIdx.x;       // 0..31 : column within tile (n offset on load)
    const int ty = threadIdx.y;       // 0..7
    const int n0 = blockIdx.x * 32;

    // Load: rows b = ty, ty+8, ty+16, ty+24 ; coalesced over n.
    #pragma unroll
    for (int k = 0; k < 4; k++) {
        int b = ty + k * 8;
        tile[b][tx] = x[(size_t)b * N + n0 + tx];
    }
    __syncthreads();

    // Store: xT[(n0+row)*32 + b], coalesced over b (tx).
    #pragma unroll
    for (int k = 0; k < 4; k++) {
        int row = ty + k * 8;
        xT[(size_t)(n0 + row) * B + tx] = tile[tx][row];
    }
}

// ---------------------------------------------------------------------------
// Kernel 2: one warp per segment n.
//   acc[lane] = sum_{d<16} k[n*16+d] * xT[src[n*16+d]*32 + lane]   (+ bias sum)
//   out[lane*N + n] = acc + bsum
// 256 threads = 8 warps = 8 consecutive segments per block.
// Edge data for the block's 128 edges staged in smem.
// ---------------------------------------------------------------------------
__global__ __launch_bounds__(256) void pc_kernel(const float* __restrict__ kern,
                                                 const float* __restrict__ bias,
                                                 const int*   __restrict__ edge_src,
                                                 const float* __restrict__ xT,
                                                 float*       __restrict__ out) {
    __shared__ int   s_src[SEGS_PER_BLOCK * DEG];
    __shared__ float s_k  [SEGS_PER_BLOCK * DEG];
    __shared__ float s_b  [SEGS_PER_BLOCK * DEG];

    const int t    = threadIdx.x;
    const int e0   = blockIdx.x * (SEGS_PER_BLOCK * DEG);

    if (t < SEGS_PER_BLOCK * DEG) {
        s_src[t] = edge_src[e0 + t];
        s_k[t]   = kern[e0 + t];
        s_b[t]   = bias[e0 + t];
    }
    __syncthreads();

    const int warp = t >> 5;
    const int lane = t & 31;
    const int n    = blockIdx.x * SEGS_PER_BLOCK + warp;
    const int base = warp * DEG;

    // Batch the 16 independent gathers (high MLP); smem reads are broadcasts.
    float acc = 0.0f;
    #pragma unroll
    for (int d = 0; d < DEG; d++) {
        int   src = s_src[base + d];
        float xv  = __ldg(&xT[(size_t)src * B + lane]);
        acc = fmaf(xv, s_k[base + d], acc);
    }

    // bias contribution is identical for every batch row of this segment
    float bsum = 0.0f;
    #pragma unroll
    for (int d = 0; d < DEG; d++) bsum += s_b[base + d];

    out[(size_t)lane * N + n] = acc + bsum;
}

// ---------------------------------------------------------------------------
// d_in order (metadata): x, kernel, bias, edge_src, segment_ids, num_units
// ---------------------------------------------------------------------------
extern "C" void kernel_launch(void* const* d_in, const int* in_sizes, int n_in,
                              void* d_out, int out_size) {
    const float* x        = (const float*)d_in[0];
    const float* kern     = (const float*)d_in[1];
    const float* bias     = (const float*)d_in[2];
    const int*   edge_src = (const int*)  d_in[3];
    float*       out      = (float*)d_out;

    float* xT;
    cudaGetSymbolAddress((void**)&xT, g_xT);

    dim3 tb(32, 8);
    transpose_kernel<<<N / 32, tb>>>(x, xT);

    pc_kernel<<<N / SEGS_PER_BLOCK, 256>>>(kern, bias, edge_src, xT, out);
}

// round 2
// speedup vs baseline: 1.2113x; 1.2113x over previous
#include <cuda_runtime.h>
#include <cuda_bf16.h>

#define B   32
#define N   100000
#define DEG 16
#define SPB 16              // segments (warps) per block; 512 threads
#define NBLK (N / SPB)      // 6250, divides exactly

// Scratch: transposed x, shape (N, 32). 12.8 MB static device array.
__device__ float g_xT[(size_t)N * B];

// ---------------------------------------------------------------------------
// Kernel 1: transpose x (B=32, N) -> x_T (N, 32)
// ---------------------------------------------------------------------------
__global__ __launch_bounds__(256) void transpose_kernel(const float* __restrict__ x,
                                                        float* __restrict__ xT) {
    __shared__ float tile[32][33];
    const int tx = threadIdx.x;       // 0..31
    const int ty = threadIdx.y;       // 0..7
    const int n0 = blockIdx.x * 32;

    #pragma unroll
    for (int k = 0; k < 4; k++) {
        int b = ty + k * 8;
        tile[b][tx] = x[(size_t)b * N + n0 + tx];
    }
    __syncthreads();

    #pragma unroll
    for (int k = 0; k < 4; k++) {
        int row = ty + k * 8;
        xT[(size_t)(n0 + row) * B + tx] = tile[tx][row];
    }
}

// ---------------------------------------------------------------------------
// Kernel 2: one warp per segment n. 16 warps/block.
//   acc[lane] = sum_d k[n*16+d] * xT[src[n*16+d]*32 + lane]  + sum_d bias
// Edge data read as uniform int4/float4 LDG (warp-broadcast, 1 wf each).
// Gathers use __ldcg (L2-only, no L1 fill; random access -> L1 hit ~0).
// Results staged in smem, written out coalesced (batch-major).
// ---------------------------------------------------------------------------
__global__ __launch_bounds__(512) void pc_kernel(const float* __restrict__ kern,
                                                 const float* __restrict__ bias,
                                                 const int*   __restrict__ edge_src,
                                                 const float* __restrict__ xT,
                                                 float*       __restrict__ out) {
    __shared__ float s_out[SPB][33];

    const int t    = threadIdx.x;
    const int warp = t >> 5;
    const int lane = t & 31;
    const int n    = blockIdx.x * SPB + warp;
    const size_t e0 = (size_t)n * DEG;   // 16-edge group, 64B aligned

    const int4*   src4 = (const int4*)  (edge_src + e0);
    const float4* k4   = (const float4*)(kern + e0);
    const float4* b4   = (const float4*)(bias + e0);

    // Uniform (warp-broadcast) edge loads: 12 LDG.128, 1 wavefront each.
    int4   s0 = __ldg(&src4[0]), s1 = __ldg(&src4[1]),
           s2 = __ldg(&src4[2]), s3 = __ldg(&src4[3]);
    float4 c0 = __ldg(&k4[0]),   c1 = __ldg(&k4[1]),
           c2 = __ldg(&k4[2]),   c3 = __ldg(&k4[3]);
    float4 bb0 = __ldg(&b4[0]),  bb1 = __ldg(&b4[1]),
           bb2 = __ldg(&b4[2]),  bb3 = __ldg(&b4[3]);

    // 16 independent coalesced gathers (128B line each), L2-only.
    float x00 = __ldcg(&xT[(size_t)s0.x * B + lane]);
    float x01 = __ldcg(&xT[(size_t)s0.y * B + lane]);
    float x02 = __ldcg(&xT[(size_t)s0.z * B + lane]);
    float x03 = __ldcg(&xT[(size_t)s0.w * B + lane]);
    float x04 = __ldcg(&xT[(size_t)s1.x * B + lane]);
    float x05 = __ldcg(&xT[(size_t)s1.y * B + lane]);
    float x06 = __ldcg(&xT[(size_t)s1.z * B + lane]);
    float x07 = __ldcg(&xT[(size_t)s1.w * B + lane]);
    float x08 = __ldcg(&xT[(size_t)s2.x * B + lane]);
    float x09 = __ldcg(&xT[(size_t)s2.y * B + lane]);
    float x10 = __ldcg(&xT[(size_t)s2.z * B + lane]);
    float x11 = __ldcg(&xT[(size_t)s2.w * B + lane]);
    float x12 = __ldcg(&xT[(size_t)s3.x * B + lane]);
    float x13 = __ldcg(&xT[(size_t)s3.y * B + lane]);
    float x14 = __ldcg(&xT[(size_t)s3.z * B + lane]);
    float x15 = __ldcg(&xT[(size_t)s3.w * B + lane]);

    float bsum = (bb0.x + bb0.y + bb0.z + bb0.w)
               + (bb1.x + bb1.y + bb1.z + bb1.w)
               + (bb2.x + bb2.y + bb2.z + bb2.w)
               + (bb3.x + bb3.y + bb3.z + bb3.w);

    float acc = bsum;
    acc = fmaf(x00, c0.x, acc);  acc = fmaf(x01, c0.y, acc);
    acc = fmaf(x02, c0.z, acc);  acc = fmaf(x03, c0.w, acc);
    acc = fmaf(x04, c1.x, acc);  acc = fmaf(x05, c1.y, acc);
    acc = fmaf(x06, c1.z, acc);  acc = fmaf(x07, c1.w, acc);
    acc = fmaf(x08, c2.x, acc);  acc = fmaf(x09, c2.y, acc);
    acc = fmaf(x10, c2.z, acc);  acc = fmaf(x11, c2.w, acc);
    acc = fmaf(x12, c3.x, acc);  acc = fmaf(x13, c3.y, acc);
    acc = fmaf(x14, c3.z, acc);  acc = fmaf(x15, c3.w, acc);

    s_out[warp][lane] = acc;
    __syncthreads();

    // Coalesced write-out: 32 batch rows x 16 consecutive segments.
    // thread t -> row b = t/16 (0..31), col = t%16; 64B per row per block.
    int row = t >> 4;
    int col = t & 15;
    out[(size_t)row * N + blockIdx.x * SPB + col] = s_out[col][row];
}

// ---------------------------------------------------------------------------
// d_in order: x, kernel, bias, edge_src, segment_ids, num_units
// ---------------------------------------------------------------------------
extern "C" void kernel_launch(void* const* d_in, const int* in_sizes, int n_in,
                              void* d_out, int out_size) {
    const float* x        = (const float*)d_in[0];
    const float* kern     = (const float*)d_in[1];
    const float* bias     = (const float*)d_in[2];
    const int*   edge_src = (const int*)  d_in[3];
    float*       out      = (float*)d_out;

    float* xT;
    cudaGetSymbolAddress((void**)&xT, g_xT);

    dim3 tb(32, 8);
    transpose_kernel<<<N / 32, tb>>>(x, xT);

    pc_kernel<<<NBLK, 512>>>(kern, bias, edge_src, xT, out);
}

// round 3
// speedup vs baseline: 1.7683x; 1.4598x over previous
#include <cuda_runtime.h>
#include <cuda_fp16.h>

#define B    32
#define N    100000
#define DEG  16
#define WPB  16                 // warps per block (512 threads)
#define SEGS_PER_BLOCK (WPB*2)  // 32 segments per block (2 per warp)
#define NBLK (N / SEGS_PER_BLOCK) // 3125, exact

// Scratch: transposed x in fp16, shape (N, 32). 6.4 MB static device array.
__device__ __half g_xT[(size_t)N * B];

// ---------------------------------------------------------------------------
// Kernel 1: transpose x (B=32, N) fp32 -> x_T (N, 32) fp16
// ---------------------------------------------------------------------------
__global__ __launch_bounds__(256) void transpose_kernel(const float* __restrict__ x,
                                                        __half* __restrict__ xT) {
    __shared__ float tile[32][33];
    const int tx = threadIdx.x;       // 0..31
    const int ty = threadIdx.y;       // 0..7
    const int n0 = blockIdx.x * 32;

    #pragma unroll
    for (int k = 0; k < 4; k++) {
        int b = ty + k * 8;
        tile[b][tx] = x[(size_t)b * N + n0 + tx];
    }
    __syncthreads();

    #pragma unroll
    for (int k = 0; k < 4; k++) {
        int row = ty + k * 8;
        xT[(size_t)(n0 + row) * B + tx] = __float2half_rn(tile[tx][row]);
    }
}

// ---------------------------------------------------------------------------
// Kernel 2: one warp handles TWO segments.
//   lanes 0-15  -> segment nA = 2*w,   lane p handles batches {2p, 2p+1}
//   lanes 16-31 -> segment nB = 2*w+1, likewise
// Each gather is one LDG.32 of half2 serving both segments (2 x 64B lines).
// Uniform edge loads are per-half-warp broadcasts (1 instr, 2 addresses).
// Accumulate fp32; stage in smem; coalesced float2 write-out.
// ---------------------------------------------------------------------------
__global__ __launch_bounds__(512) void pc_kernel(const float* __restrict__ kern,
                                                 const float* __restrict__ bias,
                                                 const int*   __restrict__ edge_src,
                                                 const __half* __restrict__ xT,
                                                 float*       __restrict__ out) {
    __shared__ float s_out[SEGS_PER_BLOCK][36];   // row stride 144B (8B aligned)

    const int t    = threadIdx.x;
    const int warp = t >> 5;
    const int lane = t & 31;
    const int half_id = lane >> 4;          // 0 = segment A, 1 = segment B
    const int p    = lane & 15;             // batch-pair index 0..15

    const int n = blockIdx.x * SEGS_PER_BLOCK + (warp << 1) + half_id;
    const size_t e0 = (size_t)n * DEG;      // 64B aligned

    const int4*   src4 = (const int4*)  (edge_src + e0);
    const float4* k4   = (const float4*)(kern + e0);
    const float4* b4   = (const float4*)(bias + e0);

    // Per-half-warp broadcast loads: 12 LDG.128 per warp, serving 2 segments.
    int4   s0 = __ldg(&src4[0]), s1 = __ldg(&src4[1]),
           s2 = __ldg(&src4[2]), s3 = __ldg(&src4[3]);
    float4 c0 = __ldg(&k4[0]),   c1 = __ldg(&k4[1]),
           c2 = __ldg(&k4[2]),   c3 = __ldg(&k4[3]);
    float4 bb0 = __ldg(&b4[0]),  bb1 = __ldg(&b4[1]),
           bb2 = __ldg(&b4[2]),  bb3 = __ldg(&b4[3]);

    // 16 gathers, each half2 = 2 batch elements; L2-only (.cg), 64B/line pair.
    const __half2* xt2 = (const __half2*)xT;
    __half2 g[16];
    g[ 0] = __ldcg(&xt2[(size_t)s0.x * (B/2) + p]);
    g[ 1] = __ldcg(&xt2[(size_t)s0.y * (B/2) + p]);
    g[ 2] = __ldcg(&xt2[(size_t)s0.z * (B/2) + p]);
    g[ 3] = __ldcg(&xt2[(size_t)s0.w * (B/2) + p]);
    g[ 4] = __ldcg(&xt2[(size_t)s1.x * (B/2) + p]);
    g[ 5] = __ldcg(&xt2[(size_t)s1.y * (B/2) + p]);
    g[ 6] = __ldcg(&xt2[(size_t)s1.z * (B/2) + p]);
    g[ 7] = __ldcg(&xt2[(size_t)s1.w * (B/2) + p]);
    g[ 8] = __ldcg(&xt2[(size_t)s2.x * (B/2) + p]);
    g[ 9] = __ldcg(&xt2[(size_t)s2.y * (B/2) + p]);
    g[10] = __ldcg(&xt2[(size_t)s2.z * (B/2) + p]);
    g[11] = __ldcg(&xt2[(size_t)s2.w * (B/2) + p]);
    g[12] = __ldcg(&xt2[(size_t)s3.x * (B/2) + p]);
    g[13] = __ldcg(&xt2[(size_t)s3.y * (B/2) + p]);
    g[14] = __ldcg(&xt2[(size_t)s3.z * (B/2) + p]);
    g[15] = __ldcg(&xt2[(size_t)s3.w * (B/2) + p]);

    float bsum = (bb0.x + bb0.y + bb0.z + bb0.w)
               + (bb1.x + bb1.y + bb1.z + bb1.w)
               + (bb2.x + bb2.y + bb2.z + bb2.w)
               + (bb3.x + bb3.y + bb3.z + bb3.w);

    float kk[16] = { c0.x, c0.y, c0.z, c0.w, c1.x, c1.y, c1.z, c1.w,
                     c2.x, c2.y, c2.z, c2.w, c3.x, c3.y, c3.z, c3.w };

    float accx = bsum, accy = bsum;
    #pragma unroll
    for (int d = 0; d < 16; d++) {
        float2 xv = __half22float2(g[d]);
        accx = fmaf(xv.x, kk[d], accx);
        accy = fmaf(xv.y, kk[d], accy);
    }

    const int seg_in_blk = (warp << 1) | half_id;      // 0..31
    s_out[seg_in_blk][2 * p]     = accx;               // batch 2p
    s_out[seg_in_blk][2 * p + 1] = accy;               // batch 2p+1
    __syncthreads();

    // Coalesced write-out: thread t -> batch row b=t/16, float2 column c=t%16.
    // out[b][n0 + 2c .. 2c+1]; 128B per row per block.
    const int row = t >> 4;
    const int col = t & 15;
    const int n0  = blockIdx.x * SEGS_PER_BLOCK;
    float2 v = make_float2(s_out[2 * col][row], s_out[2 * col + 1][row]);
    *(float2*)(out + (size_t)row * N + n0 + 2 * col) = v;
}

// ---------------------------------------------------------------------------
// d_in order: x, kernel, bias, edge_src, segment_ids, num_units
// ---------------------------------------------------------------------------
extern "C" void kernel_launch(void* const* d_in, const int* in_sizes, int n_in,
                              void* d_out, int out_size) {
    const float* x        = (const float*)d_in[0];
    const float* kern     = (const float*)d_in[1];
    const float* bias     = (const float*)d_in[2];
    const int*   edge_src = (const int*)  d_in[3];
    float*       out      = (float*)d_out;

    __half* xT;
    cudaGetSymbolAddress((void**)&xT, g_xT);

    dim3 tb(32, 8);
    transpose_kernel<<<N / 32, tb>>>(x, xT);

    pc_kernel<<<NBLK, 512>>>(kern, bias, edge_src, xT, out);
}

// round 5
// speedup vs baseline: 2.2386x; 1.2660x over previous
#include <cuda_runtime.h>
#include <cuda_fp16.h>

#define B    32
#define N    100000
#define DEG  16
#define SPB  32                  // segments per block (8 warps x 4 segs/warp)
#define NBLK (N / SPB)           // 3125, exact

// Scratch: transposed x in fp16, shape (N, 32). 6.4 MB static device array.
__device__ __half g_xT[(size_t)N * B];

// ---------------------------------------------------------------------------
// Kernel 1: transpose x (B=32, N) fp32 -> x_T (N, 32) fp16
// ---------------------------------------------------------------------------
__global__ __launch_bounds__(256) void transpose_kernel(const float* __restrict__ x,
                                                        __half* __restrict__ xT) {
    __shared__ float tile[32][33];
    const int tx = threadIdx.x;       // 0..31
    const int ty = threadIdx.y;       // 0..7
    const int n0 = blockIdx.x * 32;

    #pragma unroll
    for (int k = 0; k < 4; k++) {
        int b = ty + k * 8;
        tile[b][tx] = x[(size_t)b * N + n0 + tx];
    }
    __syncthreads();

    #pragma unroll
    for (int k = 0; k < 4; k++) {
        int row = ty + k * 8;
        xT[(size_t)(n0 + row) * B + tx] = __float2half_rn(tile[tx][row]);
    }
}

// ---------------------------------------------------------------------------
// Kernel 2: one warp handles FOUR segments.
//   quarter q = lane/8 owns segment n = blk*32 + warp*4 + q
//   lane r = lane%8 handles batches 4r..4r+3 via one uint2 (half4) gather.
// One gather LDG.64 serves all 4 segments' d-th edge. Uniform edge loads are
// quarter-warp broadcasts (1 instr, 4 addrs). fp32 accumulation; smem-staged
// conflict-free transpose; float4 coalesced write-out.
// ---------------------------------------------------------------------------
__global__ __launch_bounds__(256) void pc_kernel(const float* __restrict__ kern,
                                                 const float* __restrict__ bias,
                                                 const int*   __restrict__ edge_src,
                                                 const __half* __restrict__ xT,
                                                 float*       __restrict__ out) {
    __shared__ float s_out[SPB][33];

    const int t    = threadIdx.x;
    const int warp = t >> 5;
    const int lane = t & 31;
    const int q    = lane >> 3;             // 0..3 : segment within warp
    const int r    = lane & 7;              // 0..7 : batch-quad index

    const int seg_in_blk = (warp << 2) | q; // 0..31
    const int n  = blockIdx.x * SPB + seg_in_blk;
    const size_t e0 = (size_t)n * DEG;      // 64B aligned per segment

    const int4*   src4 = (const int4*)  (edge_src + e0);
    const float4* k4   = (const float4*)(kern + e0);
    const float4* b4   = (const float4*)(bias + e0);

    // Quarter-warp broadcast loads: 12 LDG.128 per warp serving 4 segments.
    int4   s0 = __ldcg(&src4[0]), s1 = __ldcg(&src4[1]),
           s2 = __ldcg(&src4[2]), s3 = __ldcg(&src4[3]);

    // 16 gathers, each uint2 = 4 fp16 batch elements; L2-only.
    const uint2* xt4 = (const uint2*)xT;    // row = 8 x uint2 (64B)
    uint2 g[16];
    g[ 0] = __ldcg(&xt4[(size_t)s0.x * 8 + r]);
    g[ 1] = __ldcg(&xt4[(size_t)s0.y * 8 + r]);
    g[ 2] = __ldcg(&xt4[(size_t)s0.z * 8 + r]);
    g[ 3] = __ldcg(&xt4[(size_t)s0.w * 8 + r]);
    g[ 4] = __ldcg(&xt4[(size_t)s1.x * 8 + r]);
    g[ 5] = __ldcg(&xt4[(size_t)s1.y * 8 + r]);
    g[ 6] = __ldcg(&xt4[(size_t)s1.z * 8 + r]);
    g[ 7] = __ldcg(&xt4[(size_t)s1.w * 8 + r]);
    g[ 8] = __ldcg(&xt4[(size_t)s2.x * 8 + r]);
    g[ 9] = __ldcg(&xt4[(size_t)s2.y * 8 + r]);
    g[10] = __ldcg(&xt4[(size_t)s2.z * 8 + r]);
    g[11] = __ldcg(&xt4[(size_t)s2.w * 8 + r]);
    g[12] = __ldcg(&xt4[(size_t)s3.x * 8 + r]);
    g[13] = __ldcg(&xt4[(size_t)s3.y * 8 + r]);
    g[14] = __ldcg(&xt4[(size_t)s3.z * 8 + r]);
    g[15] = __ldcg(&xt4[(size_t)s3.w * 8 + r]);

    // Coefficients + bias (overlap with outstanding gathers).
    float4 c0 = __ldcg(&k4[0]),  c1 = __ldcg(&k4[1]),
           c2 = __ldcg(&k4[2]),  c3 = __ldcg(&k4[3]);
    float4 bb0 = __ldcg(&b4[0]), bb1 = __ldcg(&b4[1]),
           bb2 = __ldcg(&b4[2]), bb3 = __ldcg(&b4[3]);

    float bsum = (bb0.x + bb0.y + bb0.z + bb0.w)
               + (bb1.x + bb1.y + bb1.z + bb1.w)
               + (bb2.x + bb2.y + bb2.z + bb2.w)
               + (bb3.x + bb3.y + bb3.z + bb3.w);

    float kk[16] = { c0.x, c0.y, c0.z, c0.w, c1.x, c1.y, c1.z, c1.w,
                     c2.x, c2.y, c2.z, c2.w, c3.x, c3.y, c3.z, c3.w };

    float a0 = bsum, a1 = bsum, a2 = bsum, a3 = bsum;
    #pragma unroll
    for (int d = 0; d < 16; d++) {
        float2 lo = __half22float2(*(const __half2*)&g[d].x);
        float2 hi = __half22float2(*(const __half2*)&g[d].y);
        a0 = fmaf(lo.x, kk[d], a0);
        a1 = fmaf(lo.y, kk[d], a1);
        a2 = fmaf(hi.x, kk[d], a2);
        a3 = fmaf(hi.y, kk[d], a3);
    }

    // Stage: s_out[seg][4r..4r+3]; banks (33*seg + 4r + j) mod 32 distinct per j.
    s_out[seg_in_blk][4 * r + 0] = a0;
    s_out[seg_in_blk][4 * r + 1] = a1;
    s_out[seg_in_blk][4 * r + 2] = a2;
    s_out[seg_in_blk][4 * r + 3] = a3;
    __syncthreads();

    // Write-out: thread t -> batch row b = t/8, float4 column c = t%8.
    // out[b][n0 + 4c .. 4c+3]; 128B contiguous per batch row per block.
    const int b = t >> 3;
    const int c = t & 7;
    const int n0 = blockIdx.x * SPB;
    float4 v = make_float4(s_out[4 * c + 0][b], s_out[4 * c + 1][b],
                           s_out[4 * c + 2][b], s_out[4 * c + 3][b]);
    *(float4*)(out + (size_t)b * N + n0 + 4 * c) = v;
}

// ---------------------------------------------------------------------------
// d_in order: x, kernel, bias, edge_src, segment_ids, num_units
// ---------------------------------------------------------------------------
extern "C" void kernel_launch(void* const* d_in, const int* in_sizes, int n_in,
                              void* d_out, int out_size) {
    const float* x        = (const float*)d_in[0];
    const float* kern     = (const float*)d_in[1];
    const float* bias     = (const float*)d_in[2];
    const int*   edge_src = (const int*)  d_in[3];
    float*       out      = (float*)d_out;

    __half* xT;
    cudaGetSymbolAddress((void**)&xT, g_xT);

    dim3 tb(32, 8);
    transpose_kernel<<<N / 32, tb>>>(x, xT);

    pc_kernel<<<NBLK, 256>>>(kern, bias, edge_src, xT, out);
}

// round 7
// speedup vs baseline: 2.2523x; 1.0061x over previous
#include <cuda_runtime.h>
#include <cuda_fp16.h>

#define B    32
#define N    100000
#define DEG  16
#define SPB  32                  // segments per block (8 warps x 4 segs/warp)
#define NBLK (N / SPB)           // 3125, exact

// Scratch: transposed x in fp16, shape (N, 32). 6.4 MB static device array.
__device__ __half g_xT[(size_t)N * B];

// ---------------------------------------------------------------------------
// Kernel 1: transpose x (B=32, N) fp32 -> x_T (N, 32) fp16
// ---------------------------------------------------------------------------
__global__ __launch_bounds__(256) void transpose_kernel(const float* __restrict__ x,
                                                        __half* __restrict__ xT) {
    __shared__ float tile[32][33];
    const int tx = threadIdx.x;       // 0..31
    const int ty = threadIdx.y;       // 0..7
    const int n0 = blockIdx.x * 32;

    #pragma unroll
    for (int k = 0; k < 4; k++) {
        int b = ty + k * 8;
        tile[b][tx] = x[(size_t)b * N + n0 + tx];
    }
    __syncthreads();

    #pragma unroll
    for (int k = 0; k < 4; k++) {
        int row = ty + k * 8;
        xT[(size_t)(n0 + row) * B + tx] = __float2half_rn(tile[tx][row]);
    }
}

// ---------------------------------------------------------------------------
// Kernel 2: one warp handles FOUR segments.
//   quarter q = lane/8 owns segment n = blk*32 + warp*4 + q
//   lane r = lane%8 handles batches 4r..4r+3 via one uint2 (half4) gather.
// One gather LDG.64 serves all 4 segments' d-th edge. Uniform edge loads are
// quarter-warp broadcasts (1 instr, 4 addrs). fp32 accumulation; smem-staged
// conflict-free transpose; float4 coalesced write-out.
// ---------------------------------------------------------------------------
__global__ __launch_bounds__(256) void pc_kernel(const float* __restrict__ kern,
                                                 const float* __restrict__ bias,
                                                 const int*   __restrict__ edge_src,
                                                 const __half* __restrict__ xT,
                                                 float*       __restrict__ out) {
    __shared__ float s_out[SPB][33];

    const int t    = threadIdx.x;
    const int warp = t >> 5;
    const int lane = t & 31;
    const int q    = lane >> 3;             // 0..3 : segment within warp
    const int r    = lane & 7;              // 0..7 : batch-quad index

    const int seg_in_blk = (warp << 2) | q; // 0..31
    const int n  = blockIdx.x * SPB + seg_in_blk;
    const size_t e0 = (size_t)n * DEG;      // 64B aligned per segment

    const int4*   src4 = (const int4*)  (edge_src + e0);
    const float4* k4   = (const float4*)(kern + e0);
    const float4* b4   = (const float4*)(bias + e0);

    // Quarter-warp broadcast loads: 12 LDG.128 per warp serving 4 segments.
    int4   s0 = __ldcg(&src4[0]), s1 = __ldcg(&src4[1]),
           s2 = __ldcg(&src4[2]), s3 = __ldcg(&src4[3]);

    // 16 gathers, each uint2 = 4 fp16 batch elements; L2-only.
    const uint2* xt4 = (const uint2*)xT;    // row = 8 x uint2 (64B)
    uint2 g[16];
    g[ 0] = __ldcg(&xt4[(size_t)s0.x * 8 + r]);
    g[ 1] = __ldcg(&xt4[(size_t)s0.y * 8 + r]);
    g[ 2] = __ldcg(&xt4[(size_t)s0.z * 8 + r]);
    g[ 3] = __ldcg(&xt4[(size_t)s0.w * 8 + r]);
    g[ 4] = __ldcg(&xt4[(size_t)s1.x * 8 + r]);
    g[ 5] = __ldcg(&xt4[(size_t)s1.y * 8 + r]);
    g[ 6] = __ldcg(&xt4[(size_t)s1.z * 8 + r]);
    g[ 7] = __ldcg(&xt4[(size_t)s1.w * 8 + r]);
    g[ 8] = __ldcg(&xt4[(size_t)s2.x * 8 + r]);
    g[ 9] = __ldcg(&xt4[(size_t)s2.y * 8 + r]);
    g[10] = __ldcg(&xt4[(size_t)s2.z * 8 + r]);
    g[11] = __ldcg(&xt4[(size_t)s2.w * 8 + r]);
    g[12] = __ldcg(&xt4[(size_t)s3.x * 8 + r]);
    g[13] = __ldcg(&xt4[(size_t)s3.y * 8 + r]);
    g[14] = __ldcg(&xt4[(size_t)s3.z * 8 + r]);
    g[15] = __ldcg(&xt4[(size_t)s3.w * 8 + r]);

    // Coefficients + bias (overlap with outstanding gathers).
    float4 c0 = __ldcg(&k4[0]),  c1 = __ldcg(&k4[1]),
           c2 = __ldcg(&k4[2]),  c3 = __ldcg(&k4[3]);
    float4 bb0 = __ldcg(&b4[0]), bb1 = __ldcg(&b4[1]),
           bb2 = __ldcg(&b4[2]), bb3 = __ldcg(&b4[3]);

    float bsum = (bb0.x + bb0.y + bb0.z + bb0.w)
               + (bb1.x + bb1.y + bb1.z + bb1.w)
               + (bb2.x + bb2.y + bb2.z + bb2.w)
               + (bb3.x + bb3.y + bb3.z + bb3.w);

    float kk[16] = { c0.x, c0.y, c0.z, c0.w, c1.x, c1.y, c1.z, c1.w,
                     c2.x, c2.y, c2.z, c2.w, c3.x, c3.y, c3.z, c3.w };

    float a0 = bsum, a1 = bsum, a2 = bsum, a3 = bsum;
    #pragma unroll
    for (int d = 0; d < 16; d++) {
        float2 lo = __half22float2(*(const __half2*)&g[d].x);
        float2 hi = __half22float2(*(const __half2*)&g[d].y);
        a0 = fmaf(lo.x, kk[d], a0);
        a1 = fmaf(lo.y, kk[d], a1);
        a2 = fmaf(hi.x, kk[d], a2);
        a3 = fmaf(hi.y, kk[d], a3);
    }

    // Stage: s_out[seg][4r..4r+3]; banks (33*seg + 4r + j) mod 32 distinct per j.
    s_out[seg_in_blk][4 * r + 0] = a0;
    s_out[seg_in_blk][4 * r + 1] = a1;
    s_out[seg_in_blk][4 * r + 2] = a2;
    s_out[seg_in_blk][4 * r + 3] = a3;
    __syncthreads();

    // Write-out: thread t -> batch row b = t/8, float4 column c = t%8.
    // out[b][n0 + 4c .. 4c+3]; 128B contiguous per batch row per block.
    const int b = t >> 3;
    const int c = t & 7;
    const int n0 = blockIdx.x * SPB;
    float4 v = make_float4(s_out[4 * c + 0][b], s_out[4 * c + 1][b],
                           s_out[4 * c + 2][b], s_out[4 * c + 3][b]);
    *(float4*)(out + (size_t)b * N + n0 + 4 * c) = v;
}

// ---------------------------------------------------------------------------
// d_in order: x, kernel, bias, edge_src, segment_ids, num_units
// ---------------------------------------------------------------------------
extern "C" void kernel_launch(void* const* d_in, const int* in_sizes, int n_in,
                              void* d_out, int out_size) {
    const float* x        = (const float*)d_in[0];
    const float* kern     = (const float*)d_in[1];
    const float* bias     = (const float*)d_in[2];
    const int*   edge_src = (const int*)  d_in[3];
    float*       out      = (float*)d_out;

    __half* xT;
    cudaGetSymbolAddress((void**)&xT, g_xT);

    dim3 tb(32, 8);
    transpose_kernel<<<N / 32, tb>>>(x, xT);

    pc_kernel<<<NBLK, 256>>>(kern, bias, edge_src, xT, out);
}